// round 13
// baseline (speedup 1.0000x reference)
#include <cuda_runtime.h>
#include <cuda_fp16.h>
#include <cstdint>

#define BATCH   2
#define SEQ     4096
#define EMB     512
#define HEADS   8
#define HDIM    64
#define WIN     512
#define STRIDE  256
#define NW      15
#define OUTROWS (NW*WIN)      // 7680
#define QKV_LD  (3*EMB)       // 1536
#define MROWS   (BATCH*SEQ)   // 8192
#define OROWS   (BATCH*OUTROWS) // 15360

// Q scale folded into projection: 0.125 * log2(e)
#define QSCALE 0.18033688011112042f

// fp16 scratch (device globals; allocation is forbidden)
__device__ __align__(256) __half g_inh[(size_t)3 * MROWS * EMB];
__device__ __align__(256) __half g_wh [(size_t)QKV_LD * EMB + (size_t)EMB * EMB];
__device__ __align__(256) __half g_qkvh[(size_t)MROWS * QKV_LD];
__device__ __align__(256) __half g_ctxh[(size_t)OROWS * EMB];

// ---------------------------------------------------------------------------
__device__ __forceinline__ uint32_t smem_u32(const void* p) {
    uint32_t a;
    asm("{ .reg .u64 t; cvta.to.shared.u64 t, %1; cvt.u32.u64 %0, t; }" : "=r"(a) : "l"(p));
    return a;
}
#define CP16(s, g)  asm volatile("cp.async.cg.shared.global [%0], [%1], 16;" :: "r"(s), "l"(g))
#define CP_COMMIT() asm volatile("cp.async.commit_group;" ::: "memory")
#define CP_WAIT1()  asm volatile("cp.async.wait_group 1;" ::: "memory")
#define CP_WAIT0()  asm volatile("cp.async.wait_group 0;" ::: "memory")

__device__ __forceinline__ void mma16816(float c[4],
                                         uint32_t a0, uint32_t a1, uint32_t a2, uint32_t a3,
                                         uint32_t b0, uint32_t b1)
{
    asm volatile(
        "mma.sync.aligned.m16n8k16.row.col.f32.f16.f16.f32 "
        "{%0,%1,%2,%3}, {%4,%5,%6,%7}, {%8,%9}, {%0,%1,%2,%3};"
        : "+f"(c[0]), "+f"(c[1]), "+f"(c[2]), "+f"(c[3])
        : "r"(a0), "r"(a1), "r"(a2), "r"(a3), "r"(b0), "r"(b1));
}

__device__ __forceinline__ void ldsm4(uint32_t r[4], const __half* base, int ld, int lane)
{
    uint32_t sa = smem_u32(base + (lane & 15) * ld + ((lane >> 4) << 3));
    asm volatile("ldmatrix.sync.aligned.m8n8.x4.shared.b16 {%0,%1,%2,%3}, [%4];"
        : "=r"(r[0]), "=r"(r[1]), "=r"(r[2]), "=r"(r[3]) : "r"(sa));
}
__device__ __forceinline__ void ldsm4t(uint32_t r[4], const __half* base, int ld, int lane)
{
    uint32_t sa = smem_u32(base + (lane & 15) * ld + ((lane >> 4) << 3));
    asm volatile("ldmatrix.sync.aligned.m8n8.x4.trans.shared.b16 {%0,%1,%2,%3}, [%4];"
        : "=r"(r[0]), "=r"(r[1]), "=r"(r[2]), "=r"(r[3]) : "r"(sa));
}

__device__ __forceinline__ uint32_t pack_h2(float x, float y)
{
    __half2 h = __floats2half2_rn(x, y);
    return *(uint32_t*)&h;
}
__device__ __forceinline__ float ex2(float x)
{
    float y;
    asm("ex2.approx.ftz.f32 %0, %1;" : "=f"(y) : "f"(x));
    return y;
}

// ---------------------------------------------------------------------------
// prep: f32 -> f16
// ---------------------------------------------------------------------------
__global__ __launch_bounds__(256) void inputs_tohalf(
    const float4* __restrict__ q, const float4* __restrict__ k, const float4* __restrict__ v,
    __half2* __restrict__ dst, int n4)
{
    int i = blockIdx.x * 256 + threadIdx.x;
    if (i >= n4) return;
    int z = blockIdx.y;
    const float4* src = (z == 0) ? q : (z == 1) ? k : v;
    float4 val = src[i];
    __half2* o = dst + (size_t)z * n4 * 2;
    o[i*2]   = __floats2half2_rn(val.x, val.y);
    o[i*2+1] = __floats2half2_rn(val.z, val.w);
}
__global__ __launch_bounds__(256) void weights_tohalf(
    const float4* __restrict__ w_in, const float4* __restrict__ w_out,
    __half2* __restrict__ dst, int n4_in, int n4_tot)
{
    int i = blockIdx.x * 256 + threadIdx.x;
    if (i >= n4_tot) return;
    float4 v = (i < n4_in) ? w_in[i] : w_out[i - n4_in];
    dst[i*2]   = __floats2half2_rn(v.x, v.y);
    dst[i*2+1] = __floats2half2_rn(v.z, v.w);
}

// ===========================================================================
// GEMM (round-11 config, known good): 128x128 tile, 8 warps (4Mx2N),
// k-chunk 32, triple-buffered cp.async, one barrier per chunk.
// ===========================================================================
#define GK    32
#define GLDH  40
#define GARR  (128*GLDH)
#define GSLOT (2*GARR)
#define GEMM_SMEM (3*GSLOT*2)     // 61440 B

template<bool WRITE_F32>
__global__ __launch_bounds__(256, 2) void gemm_mma2(
    const __half* __restrict__ Abase, const __half* __restrict__ Wbase,
    const float* __restrict__ bias_base,
    float* __restrict__ Cf_base, __half* __restrict__ Ch_base,
    int ldc, int aslice, int wslice)
{
    extern __shared__ __half gsm[];

    const int tid  = threadIdx.x;
    const int lane = tid & 31;
    const int warp = tid >> 5;
    const int wm   = warp & 3;
    const int wn   = warp >> 2;
    const int z    = blockIdx.z;

    const __half* A  = Abase + (size_t)z * aslice;
    const __half* W  = Wbase + (size_t)z * wslice;
    const float* bias = bias_base + z * EMB;
    const int m0 = blockIdx.y * 128;
    const int n0 = blockIdx.x * 128;

    float acc[2][8][4];
    #pragma unroll
    for (int i = 0; i < 2; i++)
        #pragma unroll
        for (int j = 0; j < 8; j++)
            #pragma unroll
            for (int k = 0; k < 4; k++) acc[i][j][k] = 0.f;

    const int sr  = tid >> 1;
    const int sh  = (tid & 1) * 16;

    auto stage = [&](int c, int s) {
        const __half* gA = A + (size_t)(m0 + sr) * EMB + c * GK + sh;
        const __half* gW = W + (size_t)(n0 + sr) * EMB + c * GK + sh;
        uint32_t d = smem_u32(gsm) + (uint32_t)(s * GSLOT + sr * GLDH + sh) * 2;
        CP16(d,          gA); CP16(d + 16,          gA + 8);
        CP16(d + GARR*2, gW); CP16(d + GARR*2 + 16, gW + 8);
    };

    stage(0, 0); CP_COMMIT();
    stage(1, 1); CP_COMMIT();

    for (int c = 0; c < 16; c++) {
        if (c < 15) { CP_WAIT1(); } else { CP_WAIT0(); }
        __syncthreads();
        if (c < 14) { stage(c + 2, (c + 2) % 3); CP_COMMIT(); }

        const __half* sA = gsm + (c % 3) * GSLOT;
        const __half* sW = sA + GARR;

        #pragma unroll
        for (int ks = 0; ks < GK; ks += 16) {
            uint32_t a0[4], a1[4];
            ldsm4(a0, sA + (wm * 32 + 0)  * GLDH + ks, GLDH, lane);
            ldsm4(a1, sA + (wm * 32 + 16) * GLDH + ks, GLDH, lane);
            #pragma unroll
            for (int ng = 0; ng < 4; ng++) {
                uint32_t bb[4];
                ldsm4(bb, sW + (wn * 64 + ng * 16) * GLDH + ks, GLDH, lane);
                mma16816(acc[0][2*ng],   a0[0],a0[1],a0[2],a0[3], bb[0], bb[2]);
                mma16816(acc[1][2*ng],   a1[0],a1[1],a1[2],a1[3], bb[0], bb[2]);
                mma16816(acc[0][2*ng+1], a0[0],a0[1],a0[2],a0[3], bb[1], bb[3]);
                mma16816(acc[1][2*ng+1], a1[0],a1[1],a1[2],a1[3], bb[1], bb[3]);
            }
        }
    }

    const float sc = (!WRITE_F32 && z == 0) ? QSCALE : 1.f;
    #pragma unroll
    for (int mf = 0; mf < 2; mf++) {
        #pragma unroll
        for (int nf = 0; nf < 8; nf++) {
            int m  = m0 + wm * 32 + mf * 16 + (lane >> 2);
            int nc = n0 + wn * 64 + nf * 8 + (lane & 3) * 2;
            float2 bv = *(const float2*)(bias + nc);
            float v00 = (acc[mf][nf][0] + bv.x) * sc, v01 = (acc[mf][nf][1] + bv.y) * sc;
            float v10 = (acc[mf][nf][2] + bv.x) * sc, v11 = (acc[mf][nf][3] + bv.y) * sc;
            if (WRITE_F32) {
                float* C = Cf_base + z * EMB;
                *(float2*)(C + (size_t)m * ldc + nc)       = make_float2(v00, v01);
                *(float2*)(C + (size_t)(m + 8) * ldc + nc) = make_float2(v10, v11);
            } else {
                __half* Ch = Ch_base + z * EMB;
                *(__half2*)(Ch + (size_t)m * ldc + nc)       = __floats2half2_rn(v00, v01);
                *(__half2*)(Ch + (size_t)(m + 8) * ldc + nc) = __floats2half2_rn(v10, v11);
            }
        }
    }
}

// ===========================================================================
// FlashAttention: 256 q rows/block, 8 warps x 32 rows x 64 keys.
// K/V fragment reuse doubled vs 16-row warps. Triple-buffered KV, 1 CTA/SM.
// ===========================================================================
#define ALD   72
#define KV_SZ (64*ALD)                             // 4608 halfs per array
#define H_Q    0
#define H_SLOT (256*ALD)                           // Q: 256 rows
#define ATTN_SMEM ((H_SLOT + 3*2*KV_SZ) * 2)       // 92160 bytes

__global__ __launch_bounds__(256, 1) void attn_kernel()
{
    extern __shared__ __half ash[];
    __half* QS = ash + H_Q;

    const int tid  = threadIdx.x;
    const int lane = tid & 31;
    const int warp = tid >> 5;

    const int qt = blockIdx.x;        // 0..1
    const int h  = blockIdx.y;
    const int bn = blockIdx.z;
    const int b  = bn / NW;
    const int n  = bn % NW;
    const int q0 = qt * 256;

    const size_t rowbase = (size_t)b * SEQ + n * STRIDE;

    // stage Q (256 rows x 64 halfs = 128 B/row) — one thread per row, 8x CP16
    {
        int r = tid;
        const __half* gq = g_qkvh + (rowbase + q0 + r) * QKV_LD + h * HDIM;
        uint32_t dq = smem_u32(QS + r * ALD);
        #pragma unroll
        for (int i = 0; i < 8; i++)
            CP16(dq + i * 16, gq + i * 8);
    }

    auto stageKV = [&](int kt, int s) {
        int r  = tid >> 2;
        int cb = (tid & 3) * 16;
        const __half* kp = g_qkvh + (rowbase + kt*64 + r) * QKV_LD + EMB + h * HDIM + cb;
        const __half* vp = kp + EMB;
        uint32_t base = smem_u32(ash + H_SLOT + s * 2 * KV_SZ + r * ALD + cb);
        CP16(base,           kp); CP16(base + 16,           kp + 8);
        CP16(base + KV_SZ*2, vp); CP16(base + KV_SZ*2 + 16, vp + 8);
    };

    stageKV(0, 0); CP_COMMIT();       // Q rides in group 0
    stageKV(1, 1); CP_COMMIT();

    float o0[8][4], o1[8][4];
    #pragma unroll
    for (int j = 0; j < 8; j++)
        #pragma unroll
        for (int k = 0; k < 4; k++) { o0[j][k] = 0.f; o1[j][k] = 0.f; }

    float l0r = 0.f, l1r = 0.f, l2r = 0.f, l3r = 0.f;

    const __half* Qw0 = QS + (warp * 32 + 0)  * ALD;
    const __half* Qw1 = QS + (warp * 32 + 16) * ALD;

    for (int kt = 0; kt < 8; kt++) {
        if (kt < 7) { CP_WAIT1(); } else { CP_WAIT0(); }
        __syncthreads();
        if (kt < 6) { stageKV(kt + 2, (kt + 2) % 3); CP_COMMIT(); }

        const __half* KS = ash + H_SLOT + (kt % 3) * 2 * KV_SZ;
        const __half* VS = KS + KV_SZ;

        // ---- S = Q K^T (log2 domain), 32 rows per warp ----
        float cs0[8][4], cs1[8][4];
        #pragma unroll
        for (int j = 0; j < 8; j++)
            #pragma unroll
            for (int k = 0; k < 4; k++) { cs0[j][k] = 0.f; cs1[j][k] = 0.f; }

        #pragma unroll
        for (int ks = 0; ks < 4; ks++) {
            uint32_t aq0[4], aq1[4];
            ldsm4(aq0, Qw0 + ks * 16, ALD, lane);
            ldsm4(aq1, Qw1 + ks * 16, ALD, lane);
            #pragma unroll
            for (int ng2 = 0; ng2 < 4; ng2++) {
                uint32_t bb[4];
                ldsm4(bb, KS + (ng2 * 16) * ALD + ks * 16, ALD, lane);
                mma16816(cs0[2*ng2],   aq0[0],aq0[1],aq0[2],aq0[3], bb[0], bb[2]);
                mma16816(cs0[2*ng2+1], aq0[0],aq0[1],aq0[2],aq0[3], bb[1], bb[3]);
                mma16816(cs1[2*ng2],   aq1[0],aq1[1],aq1[2],aq1[3], bb[0], bb[2]);
                mma16816(cs1[2*ng2+1], aq1[0],aq1[1],aq1[2],aq1[3], bb[1], bb[3]);
            }
        }

        // ---- P = 2^S ; lane-local sums ----
        #pragma unroll
        for (int j = 0; j < 8; j++) {
            cs0[j][0] = ex2(cs0[j][0]); cs0[j][1] = ex2(cs0[j][1]);
            cs0[j][2] = ex2(cs0[j][2]); cs0[j][3] = ex2(cs0[j][3]);
            l0r += cs0[j][0] + cs0[j][1];
            l1r += cs0[j][2] + cs0[j][3];
            cs1[j][0] = ex2(cs1[j][0]); cs1[j][1] = ex2(cs1[j][1]);
            cs1[j][2] = ex2(cs1[j][2]); cs1[j][3] = ex2(cs1[j][3]);
            l2r += cs1[j][0] + cs1[j][1];
            l3r += cs1[j][2] + cs1[j][3];
        }

        // pack P (C-frag layout == A-frag layout)
        uint32_t pa0[4][4], pa1[4][4];
        #pragma unroll
        for (int ks = 0; ks < 4; ks++) {
            pa0[ks][0] = pack_h2(cs0[2*ks][0],   cs0[2*ks][1]);
            pa0[ks][1] = pack_h2(cs0[2*ks][2],   cs0[2*ks][3]);
            pa0[ks][2] = pack_h2(cs0[2*ks+1][0], cs0[2*ks+1][1]);
            pa0[ks][3] = pack_h2(cs0[2*ks+1][2], cs0[2*ks+1][3]);
            pa1[ks][0] = pack_h2(cs1[2*ks][0],   cs1[2*ks][1]);
            pa1[ks][1] = pack_h2(cs1[2*ks][2],   cs1[2*ks][3]);
            pa1[ks][2] = pack_h2(cs1[2*ks+1][0], cs1[2*ks+1][1]);
            pa1[ks][3] = pack_h2(cs1[2*ks+1][2], cs1[2*ks+1][3]);
        }

        // ---- O += P V (V natural [key][d], trans ldmatrix; V frags shared) ----
        #pragma unroll
        for (int ks = 0; ks < 4; ks++) {
            #pragma unroll
            for (int ng2 = 0; ng2 < 4; ng2++) {
                uint32_t bb[4];
                ldsm4t(bb, VS + (ks * 16) * ALD + ng2 * 16, ALD, lane);
                mma16816(o0[2*ng2],   pa0[ks][0],pa0[ks][1],pa0[ks][2],pa0[ks][3], bb[0], bb[1]);
                mma16816(o0[2*ng2+1], pa0[ks][0],pa0[ks][1],pa0[ks][2],pa0[ks][3], bb[2], bb[3]);
                mma16816(o1[2*ng2],   pa1[ks][0],pa1[ks][1],pa1[ks][2],pa1[ks][3], bb[0], bb[1]);
                mma16816(o1[2*ng2+1], pa1[ks][0],pa1[ks][1],pa1[ks][2],pa1[ks][3], bb[2], bb[3]);
            }
        }
    }

    // ---- final row-sum reductions, normalize, write ctx ----
    l0r += __shfl_xor_sync(0xffffffffu, l0r, 1);
    l0r += __shfl_xor_sync(0xffffffffu, l0r, 2);
    l1r += __shfl_xor_sync(0xffffffffu, l1r, 1);
    l1r += __shfl_xor_sync(0xffffffffu, l1r, 2);
    l2r += __shfl_xor_sync(0xffffffffu, l2r, 1);
    l2r += __shfl_xor_sync(0xffffffffu, l2r, 2);
    l3r += __shfl_xor_sync(0xffffffffu, l3r, 1);
    l3r += __shfl_xor_sync(0xffffffffu, l3r, 2);
    float inv0 = 1.f / l0r, inv1 = 1.f / l1r;
    float inv2 = 1.f / l2r, inv3 = 1.f / l3r;

    int r = warp * 32 + (lane >> 2);
    size_t row0 = (size_t)b * OUTROWS + n * WIN + q0 + r;
    #pragma unroll
    for (int nf = 0; nf < 8; nf++) {
        int nc = h * HDIM + nf * 8 + (lane & 3) * 2;
        *(__half2*)(g_ctxh + row0 * EMB + nc) =
            __floats2half2_rn(o0[nf][0]*inv0, o0[nf][1]*inv0);
        *(__half2*)(g_ctxh + (row0 + 8) * EMB + nc) =
            __floats2half2_rn(o0[nf][2]*inv1, o0[nf][3]*inv1);
        *(__half2*)(g_ctxh + (row0 + 16) * EMB + nc) =
            __floats2half2_rn(o1[nf][0]*inv2, o1[nf][1]*inv2);
        *(__half2*)(g_ctxh + (row0 + 24) * EMB + nc) =
            __floats2half2_rn(o1[nf][2]*inv3, o1[nf][3]*inv3);
    }
}

// ===========================================================================
extern "C" void kernel_launch(void* const* d_in, const int* in_sizes, int n_in,
                              void* d_out, int out_size)
{
    (void)in_sizes; (void)n_in; (void)out_size;
    const float* query = (const float*)d_in[0];
    const float* key   = (const float*)d_in[1];
    const float* value = (const float*)d_in[2];
    const float* w_in  = (const float*)d_in[3];
    const float* b_in  = (const float*)d_in[4];
    const float* w_out = (const float*)d_in[5];
    const float* b_out = (const float*)d_in[6];
    float* out = (float*)d_out;

    __half *inh, *wh, *qkvh, *ctxh;
    cudaGetSymbolAddress((void**)&inh,  g_inh);
    cudaGetSymbolAddress((void**)&wh,   g_wh);
    cudaGetSymbolAddress((void**)&qkvh, g_qkvh);
    cudaGetSymbolAddress((void**)&ctxh, g_ctxh);

    static bool attr_set = false;
    if (!attr_set) {
        cudaFuncSetAttribute(attn_kernel, cudaFuncAttributeMaxDynamicSharedMemorySize, ATTN_SMEM);
        cudaFuncSetAttribute(gemm_mma2<false>, cudaFuncAttributeMaxDynamicSharedMemorySize, GEMM_SMEM);
        cudaFuncSetAttribute(gemm_mma2<true>,  cudaFuncAttributeMaxDynamicSharedMemorySize, GEMM_SMEM);
        attr_set = true;
    }

    const int NIN4 = MROWS * EMB / 4;
    inputs_tohalf<<<dim3(NIN4/256, 3), 256>>>(
        (const float4*)query, (const float4*)key, (const float4*)value, (__half2*)inh, NIN4);
    const int W4IN  = (QKV_LD*EMB)/4;
    const int W4TOT = W4IN + (EMB*EMB)/4;
    weights_tohalf<<<W4TOT/256, 256>>>(
        (const float4*)w_in, (const float4*)w_out, (__half2*)wh, W4IN, W4TOT);

    gemm_mma2<false><<<dim3(EMB/128, MROWS/128, 3), 256, GEMM_SMEM>>>(
        inh, wh, b_in, nullptr, qkvh, QKV_LD, MROWS*EMB, EMB*EMB);

    attn_kernel<<<dim3(WIN/256, HEADS, BATCH*NW), 256, ATTN_SMEM>>>();

    gemm_mma2<true><<<dim3(EMB/128, OROWS/128, 1), 256, GEMM_SMEM>>>(
        ctxh, wh + (size_t)QKV_LD*EMB, b_out, out, nullptr, EMB, 0, 0);
}

// round 14
// speedup vs baseline: 1.0410x; 1.0410x over previous
#include <cuda_runtime.h>
#include <cuda_fp16.h>
#include <cstdint>

#define BATCH   2
#define SEQ     4096
#define EMB     512
#define HEADS   8
#define HDIM    64
#define WIN     512
#define STRIDE  256
#define NW      15
#define OUTROWS (NW*WIN)      // 7680
#define QKV_LD  (3*EMB)       // 1536
#define MROWS   (BATCH*SEQ)   // 8192
#define OROWS   (BATCH*OUTROWS) // 15360

// Q scale folded into projection: 0.125 * log2(e)
#define QSCALE 0.18033688011112042f

// fp16 scratch (device globals; allocation is forbidden)
__device__ __align__(256) __half g_inh[(size_t)3 * MROWS * EMB];
__device__ __align__(256) __half g_wh [(size_t)QKV_LD * EMB + (size_t)EMB * EMB];
__device__ __align__(256) __half g_qkvh[(size_t)MROWS * QKV_LD];
__device__ __align__(256) __half g_ctxh[(size_t)OROWS * EMB];

// ---------------------------------------------------------------------------
__device__ __forceinline__ uint32_t smem_u32(const void* p) {
    uint32_t a;
    asm("{ .reg .u64 t; cvta.to.shared.u64 t, %1; cvt.u32.u64 %0, t; }" : "=r"(a) : "l"(p));
    return a;
}
#define CP16(s, g)  asm volatile("cp.async.cg.shared.global [%0], [%1], 16;" :: "r"(s), "l"(g))
#define CP_COMMIT() asm volatile("cp.async.commit_group;" ::: "memory")
#define CP_WAIT1()  asm volatile("cp.async.wait_group 1;" ::: "memory")
#define CP_WAIT0()  asm volatile("cp.async.wait_group 0;" ::: "memory")

__device__ __forceinline__ void mma16816(float c[4],
                                         uint32_t a0, uint32_t a1, uint32_t a2, uint32_t a3,
                                         uint32_t b0, uint32_t b1)
{
    asm volatile(
        "mma.sync.aligned.m16n8k16.row.col.f32.f16.f16.f32 "
        "{%0,%1,%2,%3}, {%4,%5,%6,%7}, {%8,%9}, {%0,%1,%2,%3};"
        : "+f"(c[0]), "+f"(c[1]), "+f"(c[2]), "+f"(c[3])
        : "r"(a0), "r"(a1), "r"(a2), "r"(a3), "r"(b0), "r"(b1));
}

__device__ __forceinline__ void ldsm4(uint32_t r[4], const __half* base, int ld, int lane)
{
    uint32_t sa = smem_u32(base + (lane & 15) * ld + ((lane >> 4) << 3));
    asm volatile("ldmatrix.sync.aligned.m8n8.x4.shared.b16 {%0,%1,%2,%3}, [%4];"
        : "=r"(r[0]), "=r"(r[1]), "=r"(r[2]), "=r"(r[3]) : "r"(sa));
}
__device__ __forceinline__ void ldsm4t(uint32_t r[4], const __half* base, int ld, int lane)
{
    uint32_t sa = smem_u32(base + (lane & 15) * ld + ((lane >> 4) << 3));
    asm volatile("ldmatrix.sync.aligned.m8n8.x4.trans.shared.b16 {%0,%1,%2,%3}, [%4];"
        : "=r"(r[0]), "=r"(r[1]), "=r"(r[2]), "=r"(r[3]) : "r"(sa));
}

__device__ __forceinline__ uint32_t pack_h2(float x, float y)
{
    __half2 h = __floats2half2_rn(x, y);
    return *(uint32_t*)&h;
}
__device__ __forceinline__ float ex2(float x)
{
    float y;
    asm("ex2.approx.ftz.f32 %0, %1;" : "=f"(y) : "f"(x));
    return y;
}

// ---------------------------------------------------------------------------
// prep: f32 -> f16
// ---------------------------------------------------------------------------
__global__ __launch_bounds__(256) void inputs_tohalf(
    const float4* __restrict__ q, const float4* __restrict__ k, const float4* __restrict__ v,
    __half2* __restrict__ dst, int n4)
{
    int i = blockIdx.x * 256 + threadIdx.x;
    if (i >= n4) return;
    int z = blockIdx.y;
    const float4* src = (z == 0) ? q : (z == 1) ? k : v;
    float4 val = src[i];
    __half2* o = dst + (size_t)z * n4 * 2;
    o[i*2]   = __floats2half2_rn(val.x, val.y);
    o[i*2+1] = __floats2half2_rn(val.z, val.w);
}
__global__ __launch_bounds__(256) void weights_tohalf(
    const float4* __restrict__ w_in, const float4* __restrict__ w_out,
    __half2* __restrict__ dst, int n4_in, int n4_tot)
{
    int i = blockIdx.x * 256 + threadIdx.x;
    if (i >= n4_tot) return;
    float4 v = (i < n4_in) ? w_in[i] : w_out[i - n4_in];
    dst[i*2]   = __floats2half2_rn(v.x, v.y);
    dst[i*2+1] = __floats2half2_rn(v.z, v.w);
}

// ===========================================================================
// GEMM (round-11 config, known good): 128x128 tile, 8 warps (4Mx2N),
// k-chunk 32, triple-buffered cp.async, one barrier per chunk.
// ===========================================================================
#define GK    32
#define GLDH  40
#define GARR  (128*GLDH)
#define GSLOT (2*GARR)
#define GEMM_SMEM (3*GSLOT*2)     // 61440 B

template<bool WRITE_F32>
__global__ __launch_bounds__(256, 2) void gemm_mma2(
    const __half* __restrict__ Abase, const __half* __restrict__ Wbase,
    const float* __restrict__ bias_base,
    float* __restrict__ Cf_base, __half* __restrict__ Ch_base,
    int ldc, int aslice, int wslice)
{
    extern __shared__ __half gsm[];

    const int tid  = threadIdx.x;
    const int lane = tid & 31;
    const int warp = tid >> 5;
    const int wm   = warp & 3;
    const int wn   = warp >> 2;
    const int z    = blockIdx.z;

    const __half* A  = Abase + (size_t)z * aslice;
    const __half* W  = Wbase + (size_t)z * wslice;
    const float* bias = bias_base + z * EMB;
    const int m0 = blockIdx.y * 128;
    const int n0 = blockIdx.x * 128;

    float acc[2][8][4];
    #pragma unroll
    for (int i = 0; i < 2; i++)
        #pragma unroll
        for (int j = 0; j < 8; j++)
            #pragma unroll
            for (int k = 0; k < 4; k++) acc[i][j][k] = 0.f;

    const int sr  = tid >> 1;
    const int sh  = (tid & 1) * 16;

    auto stage = [&](int c, int s) {
        const __half* gA = A + (size_t)(m0 + sr) * EMB + c * GK + sh;
        const __half* gW = W + (size_t)(n0 + sr) * EMB + c * GK + sh;
        uint32_t d = smem_u32(gsm) + (uint32_t)(s * GSLOT + sr * GLDH + sh) * 2;
        CP16(d,          gA); CP16(d + 16,          gA + 8);
        CP16(d + GARR*2, gW); CP16(d + GARR*2 + 16, gW + 8);
    };

    stage(0, 0); CP_COMMIT();
    stage(1, 1); CP_COMMIT();

    for (int c = 0; c < 16; c++) {
        if (c < 15) { CP_WAIT1(); } else { CP_WAIT0(); }
        __syncthreads();
        if (c < 14) { stage(c + 2, (c + 2) % 3); CP_COMMIT(); }

        const __half* sA = gsm + (c % 3) * GSLOT;
        const __half* sW = sA + GARR;

        #pragma unroll
        for (int ks = 0; ks < GK; ks += 16) {
            uint32_t a0[4], a1[4];
            ldsm4(a0, sA + (wm * 32 + 0)  * GLDH + ks, GLDH, lane);
            ldsm4(a1, sA + (wm * 32 + 16) * GLDH + ks, GLDH, lane);
            #pragma unroll
            for (int ng = 0; ng < 4; ng++) {
                uint32_t bb[4];
                ldsm4(bb, sW + (wn * 64 + ng * 16) * GLDH + ks, GLDH, lane);
                mma16816(acc[0][2*ng],   a0[0],a0[1],a0[2],a0[3], bb[0], bb[2]);
                mma16816(acc[1][2*ng],   a1[0],a1[1],a1[2],a1[3], bb[0], bb[2]);
                mma16816(acc[0][2*ng+1], a0[0],a0[1],a0[2],a0[3], bb[1], bb[3]);
                mma16816(acc[1][2*ng+1], a1[0],a1[1],a1[2],a1[3], bb[1], bb[3]);
            }
        }
    }

    const float sc = (!WRITE_F32 && z == 0) ? QSCALE : 1.f;
    #pragma unroll
    for (int mf = 0; mf < 2; mf++) {
        #pragma unroll
        for (int nf = 0; nf < 8; nf++) {
            int m  = m0 + wm * 32 + mf * 16 + (lane >> 2);
            int nc = n0 + wn * 64 + nf * 8 + (lane & 3) * 2;
            float2 bv = *(const float2*)(bias + nc);
            float v00 = (acc[mf][nf][0] + bv.x) * sc, v01 = (acc[mf][nf][1] + bv.y) * sc;
            float v10 = (acc[mf][nf][2] + bv.x) * sc, v11 = (acc[mf][nf][3] + bv.y) * sc;
            if (WRITE_F32) {
                float* C = Cf_base + z * EMB;
                *(float2*)(C + (size_t)m * ldc + nc)       = make_float2(v00, v01);
                *(float2*)(C + (size_t)(m + 8) * ldc + nc) = make_float2(v10, v11);
            } else {
                __half* Ch = Ch_base + z * EMB;
                *(__half2*)(Ch + (size_t)m * ldc + nc)       = __floats2half2_rn(v00, v01);
                *(__half2*)(Ch + (size_t)(m + 8) * ldc + nc) = __floats2half2_rn(v10, v11);
            }
        }
    }
}

// ===========================================================================
// FlashAttention (round-11 config): 128 q rows/block, 8 warps x 16 rows x
// 64 keys, triple-buffered KV, one barrier per tile, 2 CTAs/SM.
// NEW: ks=0 V-fragment prefetch (ng2=0,1) overlapping the softmax MUFU work.
// ===========================================================================
#define ALD   72
#define KV_SZ (64*ALD)                             // 4608 halfs per array
#define H_Q    0
#define H_SLOT (128*ALD)                           // 9216
#define ATTN_SMEM ((H_SLOT + 3*2*KV_SZ) * 2)       // 73728 bytes

__global__ __launch_bounds__(256, 2) void attn_kernel()
{
    extern __shared__ __half ash[];
    __half* QS = ash + H_Q;

    const int tid  = threadIdx.x;
    const int lane = tid & 31;
    const int warp = tid >> 5;

    const int qt = blockIdx.x;
    const int h  = blockIdx.y;
    const int bn = blockIdx.z;
    const int b  = bn / NW;
    const int n  = bn % NW;
    const int q0 = qt * 128;

    const size_t rowbase = (size_t)b * SEQ + n * STRIDE;

    // stage Q (128 rows x 64 halfs) — pre-scaled by QSCALE fold
    {
        int r  = tid >> 1;
        int cb = (tid & 1) * 32;
        const __half* gq = g_qkvh + (rowbase + q0 + r) * QKV_LD + h * HDIM + cb;
        uint32_t dq = smem_u32(QS + r * ALD + cb);
        CP16(dq, gq); CP16(dq+16, gq+8); CP16(dq+32, gq+16); CP16(dq+48, gq+24);
    }

    auto stageKV = [&](int kt, int s) {
        int r  = tid >> 2;
        int cb = (tid & 3) * 16;
        const __half* kp = g_qkvh + (rowbase + kt*64 + r) * QKV_LD + EMB + h * HDIM + cb;
        const __half* vp = kp + EMB;
        uint32_t base = smem_u32(ash + H_SLOT + s * 2 * KV_SZ + r * ALD + cb);
        CP16(base,           kp); CP16(base + 16,           kp + 8);
        CP16(base + KV_SZ*2, vp); CP16(base + KV_SZ*2 + 16, vp + 8);
    };

    stageKV(0, 0); CP_COMMIT();     // Q rides in group 0
    stageKV(1, 1); CP_COMMIT();

    float o[8][4];
    #pragma unroll
    for (int j = 0; j < 8; j++)
        #pragma unroll
        for (int k = 0; k < 4; k++) o[j][k] = 0.f;

    float l0r = 0.f, l1r = 0.f;   // lane-local partial row sums

    for (int kt = 0; kt < 8; kt++) {
        if (kt < 7) { CP_WAIT1(); } else { CP_WAIT0(); }
        __syncthreads();   // slot kt visible; all warps past slot (kt+2)%3 reads
        if (kt < 6) { stageKV(kt + 2, (kt + 2) % 3); CP_COMMIT(); }

        const __half* KS = ash + H_SLOT + (kt % 3) * 2 * KV_SZ;
        const __half* VS = KS + KV_SZ;

        // ---- S = Q K^T (log2 domain) ----
        float cs[8][4];
        #pragma unroll
        for (int j = 0; j < 8; j++)
            #pragma unroll
            for (int k = 0; k < 4; k++) cs[j][k] = 0.f;

        #pragma unroll
        for (int ks = 0; ks < 4; ks++) {
            uint32_t aq[4];
            ldsm4(aq, QS + (warp * 16) * ALD + ks * 16, ALD, lane);
            #pragma unroll
            for (int ng2 = 0; ng2 < 4; ng2++) {
                uint32_t bb[4];
                ldsm4(bb, KS + (ng2 * 16) * ALD + ks * 16, ALD, lane);
                mma16816(cs[2*ng2],   aq[0],aq[1],aq[2],aq[3], bb[0], bb[2]);
                mma16816(cs[2*ng2+1], aq[0],aq[1],aq[2],aq[3], bb[1], bb[3]);
            }
        }

        // ---- prefetch ks=0 V fragments (independent of softmax; overlaps
        //      the LDS latency with the MUFU/pack work below) ----
        uint32_t vpre0[4], vpre1[4];
        ldsm4t(vpre0, VS + 0,  ALD, lane);   // ks=0, d cols 0..15
        ldsm4t(vpre1, VS + 16, ALD, lane);   // ks=0, d cols 16..31

        // ---- P = 2^S ; lane-local sums ----
        #pragma unroll
        for (int j = 0; j < 8; j++) {
            cs[j][0] = ex2(cs[j][0]);
            cs[j][1] = ex2(cs[j][1]);
            cs[j][2] = ex2(cs[j][2]);
            cs[j][3] = ex2(cs[j][3]);
            l0r += cs[j][0] + cs[j][1];
            l1r += cs[j][2] + cs[j][3];
        }

        // pack P (C-frag layout == A-frag layout)
        uint32_t pa[4][4];
        #pragma unroll
        for (int ks = 0; ks < 4; ks++) {
            pa[ks][0] = pack_h2(cs[2*ks][0],   cs[2*ks][1]);
            pa[ks][1] = pack_h2(cs[2*ks][2],   cs[2*ks][3]);
            pa[ks][2] = pack_h2(cs[2*ks+1][0], cs[2*ks+1][1]);
            pa[ks][3] = pack_h2(cs[2*ks+1][2], cs[2*ks+1][3]);
        }

        // ---- O += P V (V natural [key][d], trans ldmatrix) ----
        #pragma unroll
        for (int ks = 0; ks < 4; ks++) {
            #pragma unroll
            for (int ng2 = 0; ng2 < 4; ng2++) {
                uint32_t bb[4];
                if (ks == 0 && ng2 == 0) {
                    bb[0]=vpre0[0]; bb[1]=vpre0[1]; bb[2]=vpre0[2]; bb[3]=vpre0[3];
                } else if (ks == 0 && ng2 == 1) {
                    bb[0]=vpre1[0]; bb[1]=vpre1[1]; bb[2]=vpre1[2]; bb[3]=vpre1[3];
                } else {
                    ldsm4t(bb, VS + (ks * 16) * ALD + ng2 * 16, ALD, lane);
                }
                mma16816(o[2*ng2],   pa[ks][0],pa[ks][1],pa[ks][2],pa[ks][3], bb[0], bb[1]);
                mma16816(o[2*ng2+1], pa[ks][0],pa[ks][1],pa[ks][2],pa[ks][3], bb[2], bb[3]);
            }
        }
    }

    // ---- final row-sum reduction, normalize, write ctx ----
    l0r += __shfl_xor_sync(0xffffffffu, l0r, 1);
    l0r += __shfl_xor_sync(0xffffffffu, l0r, 2);
    l1r += __shfl_xor_sync(0xffffffffu, l1r, 1);
    l1r += __shfl_xor_sync(0xffffffffu, l1r, 2);
    float inv0 = 1.f / l0r;
    float inv1 = 1.f / l1r;

    int r = warp * 16 + (lane >> 2);
    size_t row0 = (size_t)b * OUTROWS + n * WIN + q0 + r;
    #pragma unroll
    for (int nf = 0; nf < 8; nf++) {
        int nc = h * HDIM + nf * 8 + (lane & 3) * 2;
        *(__half2*)(g_ctxh + row0 * EMB + nc) =
            __floats2half2_rn(o[nf][0]*inv0, o[nf][1]*inv0);
        *(__half2*)(g_ctxh + (row0 + 8) * EMB + nc) =
            __floats2half2_rn(o[nf][2]*inv1, o[nf][3]*inv1);
    }
}

// ===========================================================================
extern "C" void kernel_launch(void* const* d_in, const int* in_sizes, int n_in,
                              void* d_out, int out_size)
{
    (void)in_sizes; (void)n_in; (void)out_size;
    const float* query = (const float*)d_in[0];
    const float* key   = (const float*)d_in[1];
    const float* value = (const float*)d_in[2];
    const float* w_in  = (const float*)d_in[3];
    const float* b_in  = (const float*)d_in[4];
    const float* w_out = (const float*)d_in[5];
    const float* b_out = (const float*)d_in[6];
    float* out = (float*)d_out;

    __half *inh, *wh, *qkvh, *ctxh;
    cudaGetSymbolAddress((void**)&inh,  g_inh);
    cudaGetSymbolAddress((void**)&wh,   g_wh);
    cudaGetSymbolAddress((void**)&qkvh, g_qkvh);
    cudaGetSymbolAddress((void**)&ctxh, g_ctxh);

    static bool attr_set = false;
    if (!attr_set) {
        cudaFuncSetAttribute(attn_kernel, cudaFuncAttributeMaxDynamicSharedMemorySize, ATTN_SMEM);
        cudaFuncSetAttribute(gemm_mma2<false>, cudaFuncAttributeMaxDynamicSharedMemorySize, GEMM_SMEM);
        cudaFuncSetAttribute(gemm_mma2<true>,  cudaFuncAttributeMaxDynamicSharedMemorySize, GEMM_SMEM);
        attr_set = true;
    }

    const int NIN4 = MROWS * EMB / 4;
    inputs_tohalf<<<dim3(NIN4/256, 3), 256>>>(
        (const float4*)query, (const float4*)key, (const float4*)value, (__half2*)inh, NIN4);
    const int W4IN  = (QKV_LD*EMB)/4;
    const int W4TOT = W4IN + (EMB*EMB)/4;
    weights_tohalf<<<W4TOT/256, 256>>>(
        (const float4*)w_in, (const float4*)w_out, (__half2*)wh, W4IN, W4TOT);

    gemm_mma2<false><<<dim3(EMB/128, MROWS/128, 3), 256, GEMM_SMEM>>>(
        inh, wh, b_in, nullptr, qkvh, QKV_LD, MROWS*EMB, EMB*EMB);

    attn_kernel<<<dim3(WIN/128, HEADS, BATCH*NW), 256, ATTN_SMEM>>>();

    gemm_mma2<true><<<dim3(EMB/128, OROWS/128, 1), 256, GEMM_SMEM>>>(
        ctxh, wh + (size_t)QKV_LD*EMB, b_out, out, nullptr, EMB, 0, 0);
}